// round 4
// baseline (speedup 1.0000x reference)
#include <cuda_runtime.h>
#include <math.h>
#include <stdint.h>

#define BB 128
#define SS 512
#define HH 512
#define NQ 8
#define TTAG 50

typedef unsigned long long u64;

// ---------------------------------------------------------------------------
// Scratch
// ---------------------------------------------------------------------------
__device__ float g_Xz[(size_t)SS * 4 * HH * BB];   // [t][gate][j][b]
__device__ float g_h2[2][HH * BB];                 // [buf][j][b]
__device__ int            g_cnt[4];
__device__ volatile int   g_gen[4];

extern __shared__ float smemf[];

__device__ __forceinline__ u64 dup2(float v) {
    u64 d; asm("mov.b64 %0,{%1,%1};" : "=l"(d) : "f"(v)); return d;
}
__device__ __forceinline__ void fma2(u64 &d, u64 a, u64 b) {
    asm("fma.rn.f32x2 %0,%1,%2,%0;" : "+l"(d) : "l"(a), "l"(b));
}
__device__ __forceinline__ float2 unpk(u64 d) {
    float2 r; asm("mov.b64 {%0,%1},%2;" : "=f"(r.x), "=f"(r.y) : "l"(d)); return r;
}
__device__ __forceinline__ float sigf(float x) { return 1.0f / (1.0f + __expf(-x)); }
__device__ __forceinline__ float tanhf_fast(float x) {
    return 1.0f - 2.0f / (__expf(2.0f * x) + 1.0f);
}

// ---------------------------------------------------------------------------
// Precompute (PROVEN R2 version): g_Xz[t][g][j][b] = x@Wih^T + bih + bhh
// BM=128 (batch), BN=128 (cols), BK=16; 256 threads, 8x8 tiles, f32x2 accs.
// ---------------------------------------------------------------------------
__global__ __launch_bounds__(256) void precompute_kernel(
    const float* __restrict__ x, const float* __restrict__ Wih,
    const float* __restrict__ bih, const float* __restrict__ bhh)
{
    __shared__ float As[16][132];
    __shared__ float Bs[16][136];

    const int t   = blockIdx.y;
    const int n0  = blockIdx.x * 128;
    const int tid = threadIdx.x;
    const int ty = tid >> 4, tx = tid & 15;
    const int m0 = ty * 8, c0 = tx * 8;

    u64 acc[8][4];
#pragma unroll
    for (int m = 0; m < 8; m++)
#pragma unroll
        for (int cp = 0; cp < 4; cp++) acc[m][cp] = 0ull;

    const int la_b = tid >> 1, la_k = (tid & 1) * 8;
    const float* xrow = x + ((size_t)la_b * SS + t) * HH;
    const int lb_c = tid >> 1, lb_k = (tid & 1) * 8;
    const float* wrow = Wih + (size_t)(n0 + lb_c) * HH;

    for (int kc = 0; kc < HH; kc += 16) {
        float4 a0 = *(const float4*)(xrow + kc + la_k);
        float4 a1 = *(const float4*)(xrow + kc + la_k + 4);
        float4 b0 = *(const float4*)(wrow + kc + lb_k);
        float4 b1 = *(const float4*)(wrow + kc + lb_k + 4);
        As[la_k + 0][la_b] = a0.x; As[la_k + 1][la_b] = a0.y;
        As[la_k + 2][la_b] = a0.z; As[la_k + 3][la_b] = a0.w;
        As[la_k + 4][la_b] = a1.x; As[la_k + 5][la_b] = a1.y;
        As[la_k + 6][la_b] = a1.z; As[la_k + 7][la_b] = a1.w;
        Bs[lb_k + 0][lb_c] = b0.x; Bs[lb_k + 1][lb_c] = b0.y;
        Bs[lb_k + 2][lb_c] = b0.z; Bs[lb_k + 3][lb_c] = b0.w;
        Bs[lb_k + 4][lb_c] = b1.x; Bs[lb_k + 5][lb_c] = b1.y;
        Bs[lb_k + 6][lb_c] = b1.z; Bs[lb_k + 7][lb_c] = b1.w;
        __syncthreads();

#pragma unroll
        for (int k = 0; k < 16; k++) {
            float4 h0 = *(const float4*)&As[k][m0];
            float4 h1 = *(const float4*)&As[k][m0 + 4];
            ulonglong2 wA = *(const ulonglong2*)&Bs[k][c0];
            ulonglong2 wB = *(const ulonglong2*)&Bs[k][c0 + 4];
            u64 w2[4] = {wA.x, wA.y, wB.x, wB.y};
            float av[8] = {h0.x, h0.y, h0.z, h0.w, h1.x, h1.y, h1.z, h1.w};
#pragma unroll
            for (int m = 0; m < 8; m++) {
                u64 ad = dup2(av[m]);
                fma2(acc[m][0], ad, w2[0]);
                fma2(acc[m][1], ad, w2[1]);
                fma2(acc[m][2], ad, w2[2]);
                fma2(acc[m][3], ad, w2[3]);
            }
        }
        __syncthreads();
    }

    float4 bi0 = *(const float4*)(bih + n0 + c0);
    float4 bi1 = *(const float4*)(bih + n0 + c0 + 4);
    float4 bh0 = *(const float4*)(bhh + n0 + c0);
    float4 bh1 = *(const float4*)(bhh + n0 + c0 + 4);
    float bias[8] = {bi0.x + bh0.x, bi0.y + bh0.y, bi0.z + bh0.z, bi0.w + bh0.w,
                     bi1.x + bh1.x, bi1.y + bh1.y, bi1.z + bh1.z, bi1.w + bh1.w};
    float vals[8][8];
#pragma unroll
    for (int m = 0; m < 8; m++)
#pragma unroll
        for (int cp = 0; cp < 4; cp++) {
            float2 v = unpk(acc[m][cp]);
            vals[m][2 * cp]     = v.x + bias[2 * cp];
            vals[m][2 * cp + 1] = v.y + bias[2 * cp + 1];
        }
#pragma unroll
    for (int cc = 0; cc < 8; cc++) {
        int col = n0 + c0 + cc;
        int g = col >> 9, j = col & 511;
        float* dst = g_Xz + ((((size_t)t * 4 + g) * HH) + j) * BB + m0;
        *(float4*)dst       = make_float4(vals[0][cc], vals[1][cc], vals[2][cc], vals[3][cc]);
        *(float4*)(dst + 4) = make_float4(vals[4][cc], vals[5][cc], vals[6][cc], vals[7][cc]);
    }
}

// ---------------------------------------------------------------------------
// Persistent LSTM recurrence, broadcast-W design.
// 128 CTAs = 32 col-groups (64 cols = 4 gates x 16 j) x 4 batch-groups (32 b).
// 256 threads = 8 warps; warp w owns cols [8w,8w+8), lane = batch row.
// Per warp-k: 2 LDS.128 (W broadcast) + 1 LDS.32 (h) + 4 fma2. No reduction.
// ---------------------------------------------------------------------------
#define RF_WS   0                        // Ws[k][c] padded 68: 512*68 floats
#define RF_HS   (512 * 68)               // hs[k][b]: 512*32
#define RF_ZB   (RF_HS + 512 * 32)       // zb[c][b] padded 33: 64*33
#define RF_CS   (RF_ZB + 64 * 33)        // cs[j][b]: 16*32
#define RF_TOT  (RF_CS + 16 * 32)        // 53824 floats = 215296 B

__device__ __forceinline__ void group_bar(int bg) {
    __threadfence();
    __syncthreads();
    if (threadIdx.x == 0) {
        int g = g_gen[bg];
        if (atomicAdd(&g_cnt[bg], 1) == 31) {
            g_cnt[bg] = 0;
            __threadfence();
            g_gen[bg] = g + 1;
        } else {
            while (g_gen[bg] == g) { __nanosleep(32); }
        }
        __threadfence();
    }
    __syncthreads();
}

__global__ void __launch_bounds__(256, 1) lstm_persistent(const float* __restrict__ Whh)
{
    float* Ws = smemf + RF_WS;
    float* hs = smemf + RF_HS;
    float* zb = smemf + RF_ZB;
    float* cs = smemf + RF_CS;

    const int tid = threadIdx.x;
    const int cg = blockIdx.x & 31, bg = blockIdx.x >> 5;
    const int j0 = cg * 16, b0 = bg * 32;
    const int w = tid >> 5, lane = tid & 31;

    // Load Whh slice once: Ws[k*68 + c], c = gate*16+jj
    for (int i = tid; i < 64 * HH; i += 256) {
        int c = i >> 9, k = i & 511;
        int gate = c >> 4, jj = c & 15;
        Ws[k * 68 + c] = Whh[(size_t)(gate * HH + j0 + jj) * HH + k];
    }
    for (int i = tid; i < 512; i += 256) cs[i] = 0.0f;
    for (int i = tid; i < HH * 32; i += 256) {
        int k = i >> 5, bb = i & 31;
        g_h2[0][k * BB + b0 + bb] = 0.0f;
    }
    group_bar(bg);

    const int gate = w >> 1;
    const int jjb  = (w & 1) * 8;
    const int wso  = w * 8;

    for (int t = 0; t < SS; t++) {
        const float* __restrict__ hcur = g_h2[t & 1];
        float* __restrict__ hnxt = g_h2[(t + 1) & 1];

        // prefetch Xz for our 8 cols (independent of the barrier)
        const float* xzp = g_Xz + (((size_t)t * 4 + gate) * HH + j0 + jjb) * BB + b0 + lane;
        float xzv[8];
#pragma unroll
        for (int cc = 0; cc < 8; cc++) xzv[cc] = __ldg(xzp + (size_t)cc * BB);

        // stage h[k][b0..b0+32) -> hs   (L1-bypass; written by peer CTAs)
        for (int i = tid; i < HH * 8; i += 256) {
            int k = i >> 3, seg = (i & 7) * 4;
            float4 v = __ldcg((const float4*)(hcur + (size_t)k * BB + b0 + seg));
            *(float4*)&hs[k * 32 + seg] = v;
        }
        __syncthreads();

        u64 acc0 = 0, acc1 = 0, acc2 = 0, acc3 = 0;
#pragma unroll 8
        for (int k = 0; k < HH; k++) {
            u64 hd = dup2(hs[k * 32 + lane]);
            ulonglong2 wA = *(const ulonglong2*)&Ws[k * 68 + wso];
            ulonglong2 wB = *(const ulonglong2*)&Ws[k * 68 + wso + 4];
            fma2(acc0, hd, wA.x);
            fma2(acc1, hd, wA.y);
            fma2(acc2, hd, wB.x);
            fma2(acc3, hd, wB.y);
        }

        // z = acc + Xz  -> zb[c][b]
        {
            float zv[8];
            float2 v0 = unpk(acc0), v1 = unpk(acc1), v2 = unpk(acc2), v3 = unpk(acc3);
            zv[0] = v0.x; zv[1] = v0.y; zv[2] = v1.x; zv[3] = v1.y;
            zv[4] = v2.x; zv[5] = v2.y; zv[6] = v3.x; zv[7] = v3.y;
#pragma unroll
            for (int cc = 0; cc < 8; cc++)
                zb[(wso + cc) * 33 + lane] = zv[cc] + xzv[cc];
        }
        __syncthreads();

        // gate fusion: 16 j x 32 b = 512 items
#pragma unroll
        for (int it = 0; it < 2; it++) {
            int idx = tid + it * 256;
            int bb = idx & 31, j = idx >> 5;
            float zi = zb[(j) * 33 + bb];
            float zf = zb[(16 + j) * 33 + bb];
            float zg = zb[(32 + j) * 33 + bb];
            float zo = zb[(48 + j) * 33 + bb];
            float cold = cs[j * 32 + bb];
            float cn = sigf(zf) * cold + sigf(zi) * tanhf_fast(zg);
            cs[j * 32 + bb] = cn;
            hnxt[(size_t)(j0 + j) * BB + b0 + bb] = sigf(zo) * tanhf_fast(cn);
        }
        group_bar(bg);
    }
}

// ---------------------------------------------------------------------------
// Quantum head + log_softmax (final h in g_h2[0], layout [j][b])
// ---------------------------------------------------------------------------
__global__ __launch_bounds__(128) void final_kernel(
    const float* __restrict__ Wf, const float* __restrict__ bf,
    const float* __restrict__ Wu, const float* __restrict__ bu,
    const float* __restrict__ Wo, const float* __restrict__ bo,
    const float* __restrict__ thf, const float* __restrict__ thu,
    const float* __restrict__ tho,
    const float* __restrict__ Wt, const float* __restrict__ bt,
    float* __restrict__ out)
{
    __shared__ float sx[HH];
    __shared__ float q[3][NQ];
    __shared__ float hout[NQ];
    __shared__ float lg[TTAG];
    __shared__ float lse;

    const int b = blockIdx.x;
    const int tid = threadIdx.x;

    for (int k = tid; k < HH; k += 128) sx[k] = g_h2[0][(size_t)k * BB + b];
    __syncthreads();

    const int w = tid >> 5, l = tid & 31;
    if (w < 3) {
        const float* W   = (w == 0) ? Wf : (w == 1) ? Wu : Wo;
        const float* bbv = (w == 0) ? bf : (w == 1) ? bu : bo;
        const float* th  = (w == 0) ? thf : (w == 1) ? thu : tho;
        for (int qq = 0; qq < NQ; qq++) {
            float s = 0.0f;
            for (int k = l; k < HH; k += 32) s += sx[k] * W[qq * HH + k];
#pragma unroll
            for (int o = 16; o > 0; o >>= 1) s += __shfl_xor_sync(0xffffffffu, s, o);
            if (l == 0) q[w][qq] = cosf(s + bbv[qq] + th[qq]);
        }
    }
    __syncthreads();

    if (tid < NQ) {
        float f = 1.0f / (1.0f + expf(-q[0][tid]));
        float g = tanhf(q[1][tid]);
        float o = 1.0f / (1.0f + expf(-q[2][tid]));
        hout[tid] = o * tanhf(f * g);
    }
    __syncthreads();

    if (tid < TTAG) {
        float s = bt[tid];
#pragma unroll
        for (int qq = 0; qq < NQ; qq++) s += hout[qq] * Wt[tid * NQ + qq];
        lg[tid] = s;
    }
    __syncthreads();

    if (tid == 0) {
        float m = lg[0];
        for (int i = 1; i < TTAG; i++) m = fmaxf(m, lg[i]);
        float sum = 0.0f;
        for (int i = 0; i < TTAG; i++) sum += expf(lg[i] - m);
        lse = m + logf(sum);
    }
    __syncthreads();

    if (tid < TTAG) out[(size_t)b * TTAG + tid] = lg[tid] - lse;
}

// ---------------------------------------------------------------------------
extern "C" void kernel_launch(void* const* d_in, const int* in_sizes, int n_in,
                              void* d_out, int out_size)
{
    const float* x   = (const float*)d_in[0];
    const float* Wih = (const float*)d_in[1];
    const float* Whh = (const float*)d_in[2];
    const float* bih = (const float*)d_in[3];
    const float* bhh = (const float*)d_in[4];
    const float* Wf  = (const float*)d_in[5];
    const float* bf  = (const float*)d_in[6];
    const float* Wu  = (const float*)d_in[9];
    const float* bu  = (const float*)d_in[10];
    const float* Wo  = (const float*)d_in[11];
    const float* bo  = (const float*)d_in[12];
    const float* thf = (const float*)d_in[13];
    const float* thu = (const float*)d_in[15];
    const float* tho = (const float*)d_in[16];
    const float* Wt  = (const float*)d_in[17];
    const float* bt  = (const float*)d_in[18];
    float* out = (float*)d_out;

    cudaFuncSetAttribute(lstm_persistent,
                         cudaFuncAttributeMaxDynamicSharedMemorySize, RF_TOT * 4);

    dim3 pg(16, SS);   // 16 n-blocks x 512 timesteps
    precompute_kernel<<<pg, 256>>>(x, Wih, bih, bhh);
    lstm_persistent<<<128, 256, RF_TOT * 4>>>(Whh);
    final_kernel<<<BB, 128>>>(Wf, bf, Wu, bu, Wo, bo, thf, thu, tho, Wt, bt, out);
}

// round 6
// speedup vs baseline: 1.4286x; 1.4286x over previous
#include <cuda_runtime.h>
#include <math.h>
#include <stdint.h>

#define BB 128
#define SS 512
#define HH 512
#define NQ 8
#define TTAG 50

typedef unsigned long long u64;

// ---------------------------------------------------------------------------
// Scratch
// ---------------------------------------------------------------------------
__device__ float g_Xz[(size_t)SS * 4 * HH * BB];   // [t][gate][j][b]
__device__ float g_h2[2][HH * BB];                 // [buf][j][b]
__device__ int            g_cnt[4];
__device__ volatile int   g_gen[4];

extern __shared__ float smemf[];

__device__ __forceinline__ u64 dup2(float v) {
    u64 d; asm("mov.b64 %0,{%1,%1};" : "=l"(d) : "f"(v)); return d;
}
__device__ __forceinline__ void fma2(u64 &d, u64 a, u64 b) {
    asm("fma.rn.f32x2 %0,%1,%2,%0;" : "+l"(d) : "l"(a), "l"(b));
}
__device__ __forceinline__ float2 unpk(u64 d) {
    float2 r; asm("mov.b64 {%0,%1},%2;" : "=f"(r.x), "=f"(r.y) : "l"(d)); return r;
}
__device__ __forceinline__ float sigf(float x) { return 1.0f / (1.0f + __expf(-x)); }
__device__ __forceinline__ float tanhf_fast(float x) {
    return 1.0f - 2.0f / (__expf(2.0f * x) + 1.0f);
}

// ---------------------------------------------------------------------------
// Precompute via mma.sync tf32 (m16n8k8). No tcgen05, no mbarrier -> no hangs.
// Per CTA: M=128 (batch rows, one timestep), N=128 cols, K=512.
// 8 warps in a 4(m) x 2(n) grid; warp tile 32x64 -> 2 m-frags x 8 n-frags.
// Smem As[k][m], Bs[k][n] with stride 136 (conflict-free fragment gathers).
// ---------------------------------------------------------------------------
__global__ __launch_bounds__(256) void precompute_mma(
    const float* __restrict__ x, const float* __restrict__ Wih,
    const float* __restrict__ bih, const float* __restrict__ bhh)
{
    __shared__ float As[16][136];   // [k][m]
    __shared__ float Bs[16][136];   // [k][n]
    __shared__ float sbias[128];

    const int t   = blockIdx.y;
    const int n0  = blockIdx.x * 128;
    const int tid = threadIdx.x;
    const int wid = tid >> 5, lane = tid & 31;
    const int wm = wid & 3, wn = wid >> 2;
    const int mb = wm * 32, nb = wn * 64;
    const int g  = lane >> 2, tg = lane & 3;

    if (tid < 128) sbias[tid] = bih[n0 + tid] + bhh[n0 + tid];

    float acc[2][8][4];
#pragma unroll
    for (int mf = 0; mf < 2; mf++)
#pragma unroll
        for (int nf = 0; nf < 8; nf++)
#pragma unroll
            for (int r = 0; r < 4; r++) acc[mf][nf][r] = 0.0f;

    // loaders
    const int la_b = tid >> 1, la_k = (tid & 1) * 8;
    const float* xrow = x + ((size_t)la_b * SS + t) * HH;
    const float* wrow = Wih + (size_t)(n0 + la_b) * HH;

    for (int kc = 0; kc < HH; kc += 16) {
        float4 a0 = *(const float4*)(xrow + kc + la_k);
        float4 a1 = *(const float4*)(xrow + kc + la_k + 4);
        float4 b0 = *(const float4*)(wrow + kc + la_k);
        float4 b1 = *(const float4*)(wrow + kc + la_k + 4);
        __syncthreads();
        As[la_k + 0][la_b] = a0.x; As[la_k + 1][la_b] = a0.y;
        As[la_k + 2][la_b] = a0.z; As[la_k + 3][la_b] = a0.w;
        As[la_k + 4][la_b] = a1.x; As[la_k + 5][la_b] = a1.y;
        As[la_k + 6][la_b] = a1.z; As[la_k + 7][la_b] = a1.w;
        Bs[la_k + 0][la_b] = b0.x; Bs[la_k + 1][la_b] = b0.y;
        Bs[la_k + 2][la_b] = b0.z; Bs[la_k + 3][la_b] = b0.w;
        Bs[la_k + 4][la_b] = b1.x; Bs[la_k + 5][la_b] = b1.y;
        Bs[la_k + 6][la_b] = b1.z; Bs[la_k + 7][la_b] = b1.w;
        __syncthreads();

#pragma unroll
        for (int ks = 0; ks < 16; ks += 8) {
            // A fragments (row-major m16k8): a0:(g,tg) a1:(g+8,tg) a2:(g,tg+4) a3:(g+8,tg+4)
            uint32_t afr[2][4];
#pragma unroll
            for (int mf = 0; mf < 2; mf++) {
                int r0 = mb + mf * 16 + g, r1 = r0 + 8;
                afr[mf][0] = __float_as_uint(As[ks + tg][r0]);
                afr[mf][1] = __float_as_uint(As[ks + tg][r1]);
                afr[mf][2] = __float_as_uint(As[ks + tg + 4][r0]);
                afr[mf][3] = __float_as_uint(As[ks + tg + 4][r1]);
            }
#pragma unroll
            for (int nf = 0; nf < 8; nf++) {
                // B fragment (col-major k8n8): b0:(tg, g) b1:(tg+4, g)
                int cn = nb + nf * 8 + g;
                uint32_t bf0 = __float_as_uint(Bs[ks + tg][cn]);
                uint32_t bf1 = __float_as_uint(Bs[ks + tg + 4][cn]);
#pragma unroll
                for (int mf = 0; mf < 2; mf++) {
                    asm volatile(
                        "mma.sync.aligned.m16n8k8.row.col.f32.tf32.tf32.f32 "
                        "{%0,%1,%2,%3}, {%4,%5,%6,%7}, {%8,%9}, {%0,%1,%2,%3};"
                        : "+f"(acc[mf][nf][0]), "+f"(acc[mf][nf][1]),
                          "+f"(acc[mf][nf][2]), "+f"(acc[mf][nf][3])
                        : "r"(afr[mf][0]), "r"(afr[mf][1]),
                          "r"(afr[mf][2]), "r"(afr[mf][3]),
                          "r"(bf0), "r"(bf1));
                }
            }
        }
    }

    // epilogue: d regs -> g_Xz[t][gate][j][b] (+bias)
    // c0:(row g, col 2tg) c1:(g, 2tg+1) c2:(g+8, 2tg) c3:(g+8, 2tg+1)
#pragma unroll
    for (int mf = 0; mf < 2; mf++) {
#pragma unroll
        for (int nf = 0; nf < 8; nf++) {
            int lcol = nb + nf * 8 + 2 * tg;       // 0..127 within CTA
            int row0 = mb + mf * 16 + g;           // batch row
            int row1 = row0 + 8;
#pragma unroll
            for (int cc = 0; cc < 2; cc++) {
                int gcol = n0 + lcol + cc;
                int gate = gcol >> 9, j = gcol & 511;
                float bias = sbias[lcol + cc];
                float* dst = g_Xz + (((size_t)t * 4 + gate) * HH + j) * BB;
                dst[row0] = acc[mf][nf][cc]     + bias;
                dst[row1] = acc[mf][nf][2 + cc] + bias;
            }
        }
    }
}

// ---------------------------------------------------------------------------
// Persistent LSTM recurrence (PROVEN R2 split-K design, verbatim).
// ---------------------------------------------------------------------------
#define RSM_WS   0                    // [512][68] floats
#define RSM_HS   (512 * 68)           // [512][32] staging / [8][32][64] partials
#define RSM_ZB   (RSM_HS + 512 * 32)  // [64][33] z buffer
#define RSM_CS   (RSM_ZB + 64 * 33)   // [16][32] cell state
#define RSM_TOT  (RSM_CS + 16 * 32)   // 53824 floats = 215296 B

__device__ __forceinline__ void group_bar(int bg) {
    __threadfence();
    __syncthreads();
    if (threadIdx.x == 0) {
        int g = g_gen[bg];
        if (atomicAdd(&g_cnt[bg], 1) == 31) {
            g_cnt[bg] = 0;
            __threadfence();
            g_gen[bg] = g + 1;
        } else {
            while (g_gen[bg] == g) { __nanosleep(64); }
        }
        __threadfence();
    }
    __syncthreads();
}

__global__ void __launch_bounds__(256, 1) lstm_persistent(const float* __restrict__ Whh)
{
    float* Ws  = smemf + RSM_WS;
    float* hsp = smemf + RSM_HS;
    float* zb  = smemf + RSM_ZB;
    float* cs  = smemf + RSM_CS;

    const int tid = threadIdx.x;
    const int cg = blockIdx.x & 31, bg = blockIdx.x >> 5;
    const int j0 = cg * 16, b0 = bg * 32;

    for (int i = tid; i < 64 * 128; i += 256) {
        int c = i & 63;
        int kq = i >> 6;
        int gate = c >> 4, jj = c & 15;
        const float* src = Whh + (size_t)(gate * HH + j0 + jj) * HH + kq * 4;
        float4 v = *(const float4*)src;
        float* d = Ws + (kq * 4) * 68 + c;
        d[0 * 68] = v.x; d[1 * 68] = v.y; d[2 * 68] = v.z; d[3 * 68] = v.w;
    }
    for (int i = tid; i < 512; i += 256) cs[i] = 0.0f;
    for (int i = tid; i < 512 * 32; i += 256) {
        int k = i >> 5, bb = i & 31;
        g_h2[0][k * BB + b0 + bb] = 0.0f;
    }
    group_bar(bg);

    const int w = tid >> 5, lane = tid & 31;
    const int ct = lane & 7, bt = lane >> 3;
    const int c0 = ct * 8, bl = bt * 8;
    const int kbase = w * 64;

    for (int t = 0; t < SS; t++) {
        const float* __restrict__ hcur = g_h2[t & 1];
        float* __restrict__ hnxt = g_h2[(t + 1) & 1];

        for (int i = tid; i < 512 * 8; i += 256) {
            int k = i >> 3, seg = (i & 7) * 4;
            float4 v = __ldcg((const float4*)(hcur + (size_t)k * BB + b0 + seg));
            *(float4*)&hsp[k * 32 + seg] = v;
        }
        __syncthreads();

        u64 acc[8][4];
#pragma unroll
        for (int b = 0; b < 8; b++)
#pragma unroll
            for (int cp = 0; cp < 4; cp++) acc[b][cp] = 0ull;

#pragma unroll 4
        for (int kk = 0; kk < 64; kk++) {
            int k = kbase + kk;
            float4 h0 = *(const float4*)&hsp[k * 32 + bl];
            float4 h1 = *(const float4*)&hsp[k * 32 + bl + 4];
            ulonglong2 wA = *(const ulonglong2*)&Ws[k * 68 + c0];
            ulonglong2 wB = *(const ulonglong2*)&Ws[k * 68 + c0 + 4];
            u64 w2[4] = {wA.x, wA.y, wB.x, wB.y};
            float hv[8] = {h0.x, h0.y, h0.z, h0.w, h1.x, h1.y, h1.z, h1.w};
#pragma unroll
            for (int b = 0; b < 8; b++) {
                u64 hd = dup2(hv[b]);
                fma2(acc[b][0], hd, w2[0]);
                fma2(acc[b][1], hd, w2[1]);
                fma2(acc[b][2], hd, w2[2]);
                fma2(acc[b][3], hd, w2[3]);
            }
        }
        __syncthreads();

#pragma unroll
        for (int b = 0; b < 8; b++) {
            float* p = hsp + ((size_t)(w * 32) + bl + b) * 64 + c0;
#pragma unroll
            for (int cp = 0; cp < 4; cp++) *(u64*)(p + cp * 2) = acc[b][cp];
        }
        __syncthreads();

        {
            int bb = tid & 31;
            int c0r = (tid >> 5) * 8;
            float s[8] = {0, 0, 0, 0, 0, 0, 0, 0};
#pragma unroll
            for (int ww = 0; ww < 8; ww++) {
                const float* p = hsp + ((size_t)(ww * 32) + bb) * 64 + c0r;
                float4 r0 = *(const float4*)p;
                float4 r1 = *(const float4*)(p + 4);
                s[0] += r0.x; s[1] += r0.y; s[2] += r0.z; s[3] += r0.w;
                s[4] += r1.x; s[5] += r1.y; s[6] += r1.z; s[7] += r1.w;
            }
            int g = c0r >> 4, jjb = c0r & 15;
            const float* xz = g_Xz + ((((size_t)t * 4 + g) * HH) + j0 + jjb) * BB + b0 + bb;
#pragma unroll
            for (int i = 0; i < 8; i++) s[i] += xz[(size_t)i * BB];
#pragma unroll
            for (int i = 0; i < 8; i++) zb[(c0r + i) * 33 + bb] = s[i];
        }
        __syncthreads();

#pragma unroll
        for (int it = 0; it < 2; it++) {
            int idx = tid + it * 256;
            int bb = idx & 31, j = idx >> 5;
            float zi = zb[(j)*33 + bb];
            float zf = zb[(16 + j) * 33 + bb];
            float zg = zb[(32 + j) * 33 + bb];
            float zo = zb[(48 + j) * 33 + bb];
            float cold = cs[j * 32 + bb];
            float cn = sigf(zf) * cold + sigf(zi) * tanhf_fast(zg);
            cs[j * 32 + bb] = cn;
            hnxt[(size_t)(j0 + j) * BB + b0 + bb] = sigf(zo) * tanhf_fast(cn);
        }
        group_bar(bg);
    }
}

// ---------------------------------------------------------------------------
// Quantum head + log_softmax (final h in g_h2[0], layout [j][b])
// ---------------------------------------------------------------------------
__global__ __launch_bounds__(128) void final_kernel(
    const float* __restrict__ Wf, const float* __restrict__ bf,
    const float* __restrict__ Wu, const float* __restrict__ bu,
    const float* __restrict__ Wo, const float* __restrict__ bo,
    const float* __restrict__ thf, const float* __restrict__ thu,
    const float* __restrict__ tho,
    const float* __restrict__ Wt, const float* __restrict__ bt,
    float* __restrict__ out)
{
    __shared__ float sx[HH];
    __shared__ float q[3][NQ];
    __shared__ float hout[NQ];
    __shared__ float lg[TTAG];
    __shared__ float lse;

    const int b = blockIdx.x;
    const int tid = threadIdx.x;

    for (int k = tid; k < HH; k += 128) sx[k] = g_h2[0][(size_t)k * BB + b];
    __syncthreads();

    const int w = tid >> 5, l = tid & 31;
    if (w < 3) {
        const float* W   = (w == 0) ? Wf : (w == 1) ? Wu : Wo;
        const float* bbv = (w == 0) ? bf : (w == 1) ? bu : bo;
        const float* th  = (w == 0) ? thf : (w == 1) ? thu : tho;
        for (int qq = 0; qq < NQ; qq++) {
            float s = 0.0f;
            for (int k = l; k < HH; k += 32) s += sx[k] * W[qq * HH + k];
#pragma unroll
            for (int o = 16; o > 0; o >>= 1) s += __shfl_xor_sync(0xffffffffu, s, o);
            if (l == 0) q[w][qq] = cosf(s + bbv[qq] + th[qq]);
        }
    }
    __syncthreads();

    if (tid < NQ) {
        float f = 1.0f / (1.0f + expf(-q[0][tid]));
        float g = tanhf(q[1][tid]);
        float o = 1.0f / (1.0f + expf(-q[2][tid]));
        hout[tid] = o * tanhf(f * g);
    }
    __syncthreads();

    if (tid < TTAG) {
        float s = bt[tid];
#pragma unroll
        for (int qq = 0; qq < NQ; qq++) s += hout[qq] * Wt[tid * NQ + qq];
        lg[tid] = s;
    }
    __syncthreads();

    if (tid == 0) {
        float m = lg[0];
        for (int i = 1; i < TTAG; i++) m = fmaxf(m, lg[i]);
        float sum = 0.0f;
        for (int i = 0; i < TTAG; i++) sum += expf(lg[i] - m);
        lse = m + logf(sum);
    }
    __syncthreads();

    if (tid < TTAG) out[(size_t)b * TTAG + tid] = lg[tid] - lse;
}

// ---------------------------------------------------------------------------
extern "C" void kernel_launch(void* const* d_in, const int* in_sizes, int n_in,
                              void* d_out, int out_size)
{
    const float* x   = (const float*)d_in[0];
    const float* Wih = (const float*)d_in[1];
    const float* Whh = (const float*)d_in[2];
    const float* bih = (const float*)d_in[3];
    const float* bhh = (const float*)d_in[4];
    const float* Wf  = (const float*)d_in[5];
    const float* bf  = (const float*)d_in[6];
    const float* Wu  = (const float*)d_in[9];
    const float* bu  = (const float*)d_in[10];
    const float* Wo  = (const float*)d_in[11];
    const float* bo  = (const float*)d_in[12];
    const float* thf = (const float*)d_in[13];
    const float* thu = (const float*)d_in[15];
    const float* tho = (const float*)d_in[16];
    const float* Wt  = (const float*)d_in[17];
    const float* bt  = (const float*)d_in[18];
    float* out = (float*)d_out;

    cudaFuncSetAttribute(lstm_persistent,
                         cudaFuncAttributeMaxDynamicSharedMemorySize, RSM_TOT * 4);

    dim3 pg(16, SS);   // 16 n-blocks x 512 timesteps
    precompute_mma<<<pg, 256>>>(x, Wih, bih, bhh);
    lstm_persistent<<<128, 256, RSM_TOT * 4>>>(Whh);
    final_kernel<<<BB, 128>>>(Wf, bf, Wu, bu, Wo, bo, thf, thu, tho, Wt, bt, out);
}

// round 7
// speedup vs baseline: 2.1159x; 1.4811x over previous
#include <cuda_runtime.h>
#include <math.h>
#include <stdint.h>

#define BB 128
#define SS 512
#define HH 512
#define NQ 8
#define TTAG 50

typedef unsigned long long u64;

// ---------------------------------------------------------------------------
// Scratch
// ---------------------------------------------------------------------------
__device__ float g_Xz[(size_t)SS * 4 * HH * BB];   // [t][gate][j][b]
__device__ float g_h2[2][BB * HH];                 // [buf][b][j]  (b-major)
__device__ int            g_cnt[4];
__device__ volatile int   g_gen[4];

extern __shared__ float smemf[];

__device__ __forceinline__ float sigf(float x) { return 1.0f / (1.0f + __expf(-x)); }
__device__ __forceinline__ float tanhf_fast(float x) {
    return 1.0f - 2.0f / (__expf(2.0f * x) + 1.0f);
}

#define MMA_TF32(acc, a, b0v, b1v) \
    asm volatile( \
        "mma.sync.aligned.m16n8k8.row.col.f32.tf32.tf32.f32 " \
        "{%0,%1,%2,%3}, {%4,%5,%6,%7}, {%8,%9}, {%0,%1,%2,%3};" \
        : "+f"((acc)[0]), "+f"((acc)[1]), "+f"((acc)[2]), "+f"((acc)[3]) \
        : "r"((a)[0]), "r"((a)[1]), "r"((a)[2]), "r"((a)[3]), \
          "r"(b0v), "r"(b1v))

// ---------------------------------------------------------------------------
// Precompute via mma.sync tf32 (unchanged from R6, proven).
// Per CTA: M=128 (batch, one t), N=128 cols, K=512.
// ---------------------------------------------------------------------------
__global__ __launch_bounds__(256) void precompute_mma(
    const float* __restrict__ x, const float* __restrict__ Wih,
    const float* __restrict__ bih, const float* __restrict__ bhh)
{
    __shared__ float As[16][136];
    __shared__ float Bs[16][136];
    __shared__ float sbias[128];

    const int t   = blockIdx.y;
    const int n0  = blockIdx.x * 128;
    const int tid = threadIdx.x;
    const int wid = tid >> 5, lane = tid & 31;
    const int wm = wid & 3, wn = wid >> 2;
    const int mb = wm * 32, nb = wn * 64;
    const int g  = lane >> 2, tg = lane & 3;

    if (tid < 128) sbias[tid] = bih[n0 + tid] + bhh[n0 + tid];

    float acc[2][8][4];
#pragma unroll
    for (int mf = 0; mf < 2; mf++)
#pragma unroll
        for (int nf = 0; nf < 8; nf++)
#pragma unroll
            for (int r = 0; r < 4; r++) acc[mf][nf][r] = 0.0f;

    const int la_b = tid >> 1, la_k = (tid & 1) * 8;
    const float* xrow = x + ((size_t)la_b * SS + t) * HH;
    const float* wrow = Wih + (size_t)(n0 + la_b) * HH;

    for (int kc = 0; kc < HH; kc += 16) {
        float4 a0 = *(const float4*)(xrow + kc + la_k);
        float4 a1 = *(const float4*)(xrow + kc + la_k + 4);
        float4 b0 = *(const float4*)(wrow + kc + la_k);
        float4 b1 = *(const float4*)(wrow + kc + la_k + 4);
        __syncthreads();
        As[la_k + 0][la_b] = a0.x; As[la_k + 1][la_b] = a0.y;
        As[la_k + 2][la_b] = a0.z; As[la_k + 3][la_b] = a0.w;
        As[la_k + 4][la_b] = a1.x; As[la_k + 5][la_b] = a1.y;
        As[la_k + 6][la_b] = a1.z; As[la_k + 7][la_b] = a1.w;
        Bs[la_k + 0][la_b] = b0.x; Bs[la_k + 1][la_b] = b0.y;
        Bs[la_k + 2][la_b] = b0.z; Bs[la_k + 3][la_b] = b0.w;
        Bs[la_k + 4][la_b] = b1.x; Bs[la_k + 5][la_b] = b1.y;
        Bs[la_k + 6][la_b] = b1.z; Bs[la_k + 7][la_b] = b1.w;
        __syncthreads();

#pragma unroll
        for (int ks = 0; ks < 16; ks += 8) {
            uint32_t afr[2][4];
#pragma unroll
            for (int mf = 0; mf < 2; mf++) {
                int r0 = mb + mf * 16 + g, r1 = r0 + 8;
                afr[mf][0] = __float_as_uint(As[ks + tg][r0]);
                afr[mf][1] = __float_as_uint(As[ks + tg][r1]);
                afr[mf][2] = __float_as_uint(As[ks + tg + 4][r0]);
                afr[mf][3] = __float_as_uint(As[ks + tg + 4][r1]);
            }
#pragma unroll
            for (int nf = 0; nf < 8; nf++) {
                int cn = nb + nf * 8 + g;
                uint32_t bf0 = __float_as_uint(Bs[ks + tg][cn]);
                uint32_t bf1 = __float_as_uint(Bs[ks + tg + 4][cn]);
#pragma unroll
                for (int mf = 0; mf < 2; mf++) MMA_TF32(acc[mf][nf], afr[mf], bf0, bf1);
            }
        }
    }

#pragma unroll
    for (int mf = 0; mf < 2; mf++) {
#pragma unroll
        for (int nf = 0; nf < 8; nf++) {
            int lcol = nb + nf * 8 + 2 * tg;
            int row0 = mb + mf * 16 + g;
            int row1 = row0 + 8;
#pragma unroll
            for (int cc = 0; cc < 2; cc++) {
                int gcol = n0 + lcol + cc;
                int gate = gcol >> 9, j = gcol & 511;
                float bias = sbias[lcol + cc];
                float* dst = g_Xz + (((size_t)t * 4 + gate) * HH + j) * BB;
                dst[row0] = acc[mf][nf][cc]     + bias;
                dst[row1] = acc[mf][nf][2 + cc] + bias;
            }
        }
    }
}

// ---------------------------------------------------------------------------
// Persistent LSTM recurrence — tensor-core per-step GEMM.
// 128 CTAs = 32 col-groups (64 cols) x 4 batch-groups (32 b).
// Per step per CTA: z[32b x 64c] = h[32 x 512] @ Ws[512 x 64] via m16n8k8 tf32.
// 8 warps = 2 n-halves (32 cols) x 4 k-slices (128 k). Warp tile 32x32,
// smem partial reduction (reuses hs region), CTA-local gate fusion.
// ---------------------------------------------------------------------------
#define RT_WS   0                        // Ws[c][k] stride 516: 64*516
#define RT_HS   (64 * 516)               // hs[b][k] stride 516: 32*516 (partials reuse)
#define RT_ZB   (RT_HS + 32 * 516)       // zb[c][b] stride 33: 64*33
#define RT_CS   (RT_ZB + 64 * 33)        // cs[j][b]: 16*32
#define RT_TOT  (RT_CS + 16 * 32)        // 52160 floats = 208640 B

__device__ __forceinline__ void group_bar(int bg) {
    __threadfence();
    __syncthreads();
    if (threadIdx.x == 0) {
        int g = g_gen[bg];
        if (atomicAdd(&g_cnt[bg], 1) == 31) {
            g_cnt[bg] = 0;
            __threadfence();
            g_gen[bg] = g + 1;
        } else {
            while (g_gen[bg] == g) { __nanosleep(64); }
        }
        __threadfence();
    }
    __syncthreads();
}

__global__ void __launch_bounds__(256, 1) lstm_persistent(const float* __restrict__ Whh)
{
    float* Ws = smemf + RT_WS;
    float* hs = smemf + RT_HS;     // also partial buffer after MMA
    float* zb = smemf + RT_ZB;
    float* cs = smemf + RT_CS;

    const int tid = threadIdx.x;
    const int cg = blockIdx.x & 31, bg = blockIdx.x >> 5;
    const int j0 = cg * 16, b0 = bg * 32;
    const int w = tid >> 5, lane = tid & 31;
    const int g = lane >> 2, tg = lane & 3;

    // Load Whh slice: Ws[c][k], c = gate*16 + jj  (64 rows x 512 k, stride 516)
    for (int i = tid; i < 64 * 128; i += 256) {
        int c = i >> 7, k4 = (i & 127) * 4;
        int gate = c >> 4, jj = c & 15;
        float4 v = *(const float4*)(Whh + (size_t)(gate * HH + j0 + jj) * HH + k4);
        *(float4*)&Ws[c * 516 + k4] = v;
    }
    for (int i = tid; i < 512; i += 256) cs[i] = 0.0f;
    for (int i = tid; i < 32 * HH; i += 256) {
        int bb = i >> 9, j = i & 511;
        g_h2[0][(size_t)(b0 + bb) * HH + j] = 0.0f;
    }
    group_bar(bg);

    const int ng  = w & 1;          // n-half: cols [32ng, 32ng+32)
    const int ksl = w >> 1;         // k-slice: [128ksl, 128ksl+128)
    const int nb  = ng * 32;
    const int kb  = ksl * 128;

    for (int t = 0; t < SS; t++) {
        const float* __restrict__ hcur = g_h2[t & 1];
        float* __restrict__ hnxt = g_h2[(t + 1) & 1];

        // prefetch Xz for fusion (bb = lane, coalesced)
        float xzv[2][4];
        {
            const int bb = tid & 31;
#pragma unroll
            for (int it = 0; it < 2; it++) {
                int j = (tid + it * 256) >> 5;
#pragma unroll
                for (int gt = 0; gt < 4; gt++)
                    xzv[it][gt] = __ldg(g_Xz + (((size_t)t * 4 + gt) * HH + j0 + j) * BB + b0 + bb);
            }
        }

        // stage h rows b0..b0+31 -> hs[b][k] (stride 516); L1-bypass
        for (int i = tid; i < 32 * 128; i += 256) {
            int bb = i >> 7, k4 = (i & 127) * 4;
            float4 v = __ldcg((const float4*)(hcur + (size_t)(b0 + bb) * HH + k4));
            *(float4*)&hs[bb * 516 + k4] = v;
        }
        __syncthreads();

        // MMA: warp tile [32b x 32c] over its k-slice
        float acc[2][4][4];
#pragma unroll
        for (int mf = 0; mf < 2; mf++)
#pragma unroll
            for (int nf = 0; nf < 4; nf++)
#pragma unroll
                for (int r = 0; r < 4; r++) acc[mf][nf][r] = 0.0f;

#pragma unroll 4
        for (int kf = 0; kf < 16; kf++) {
            const int k = kb + kf * 8;
            uint32_t afr[2][4];
#pragma unroll
            for (int mf = 0; mf < 2; mf++) {
                int r0 = mf * 16 + g, r1 = r0 + 8;
                afr[mf][0] = __float_as_uint(hs[r0 * 516 + k + tg]);
                afr[mf][1] = __float_as_uint(hs[r1 * 516 + k + tg]);
                afr[mf][2] = __float_as_uint(hs[r0 * 516 + k + tg + 4]);
                afr[mf][3] = __float_as_uint(hs[r1 * 516 + k + tg + 4]);
            }
#pragma unroll
            for (int nf = 0; nf < 4; nf++) {
                int c = nb + nf * 8 + g;
                uint32_t bf0 = __float_as_uint(Ws[c * 516 + k + tg]);
                uint32_t bf1 = __float_as_uint(Ws[c * 516 + k + tg + 4]);
#pragma unroll
                for (int mf = 0; mf < 2; mf++) MMA_TF32(acc[mf][nf], afr[mf], bf0, bf1);
            }
        }
        __syncthreads();   // hs reads done; reuse as partial buffer

        // write partials: part[(ksl*64 + c)*33 + brow]
#pragma unroll
        for (int mf = 0; mf < 2; mf++)
#pragma unroll
            for (int nf = 0; nf < 4; nf++) {
                int cb = nb + nf * 8 + 2 * tg;
                int r0 = mf * 16 + g, r1 = r0 + 8;
                hs[(ksl * 64 + cb)     * 33 + r0] = acc[mf][nf][0];
                hs[(ksl * 64 + cb + 1) * 33 + r0] = acc[mf][nf][1];
                hs[(ksl * 64 + cb)     * 33 + r1] = acc[mf][nf][2];
                hs[(ksl * 64 + cb + 1) * 33 + r1] = acc[mf][nf][3];
            }
        __syncthreads();

        // reduce 4 k-slices -> zb[c][b] (stride 33)
        {
            int bb = tid & 31;
            int c0 = (tid >> 5) * 8;
#pragma unroll
            for (int i = 0; i < 8; i++) {
                int c = c0 + i;
                float s = hs[(c) * 33 + bb] + hs[(64 + c) * 33 + bb]
                        + hs[(128 + c) * 33 + bb] + hs[(192 + c) * 33 + bb];
                zb[c * 33 + bb] = s;
            }
        }
        __syncthreads();

        // gate fusion: (j, bb) items; z = zb + Xz
#pragma unroll
        for (int it = 0; it < 2; it++) {
            int idx = tid + it * 256;
            int bb = idx & 31, j = idx >> 5;
            float zi = zb[(j)      * 33 + bb] + xzv[it][0];
            float zf = zb[(16 + j) * 33 + bb] + xzv[it][1];
            float zg = zb[(32 + j) * 33 + bb] + xzv[it][2];
            float zo = zb[(48 + j) * 33 + bb] + xzv[it][3];
            float cold = cs[j * 32 + bb];
            float cn = sigf(zf) * cold + sigf(zi) * tanhf_fast(zg);
            cs[j * 32 + bb] = cn;
            hnxt[(size_t)(b0 + bb) * HH + j0 + j] = sigf(zo) * tanhf_fast(cn);
        }
        group_bar(bg);
    }
}

// ---------------------------------------------------------------------------
// Quantum head + log_softmax (final h in g_h2[0], layout [b][j])
// ---------------------------------------------------------------------------
__global__ __launch_bounds__(128) void final_kernel(
    const float* __restrict__ Wf, const float* __restrict__ bf,
    const float* __restrict__ Wu, const float* __restrict__ bu,
    const float* __restrict__ Wo, const float* __restrict__ bo,
    const float* __restrict__ thf, const float* __restrict__ thu,
    const float* __restrict__ tho,
    const float* __restrict__ Wt, const float* __restrict__ bt,
    float* __restrict__ out)
{
    __shared__ float sx[HH];
    __shared__ float q[3][NQ];
    __shared__ float hout[NQ];
    __shared__ float lg[TTAG];
    __shared__ float lse;

    const int b = blockIdx.x;
    const int tid = threadIdx.x;

    for (int k = tid; k < HH; k += 128) sx[k] = g_h2[0][(size_t)b * HH + k];
    __syncthreads();

    const int w = tid >> 5, l = tid & 31;
    if (w < 3) {
        const float* W   = (w == 0) ? Wf : (w == 1) ? Wu : Wo;
        const float* bbv = (w == 0) ? bf : (w == 1) ? bu : bo;
        const float* th  = (w == 0) ? thf : (w == 1) ? thu : tho;
        for (int qq = 0; qq < NQ; qq++) {
            float s = 0.0f;
            for (int k = l; k < HH; k += 32) s += sx[k] * W[qq * HH + k];
#pragma unroll
            for (int o = 16; o > 0; o >>= 1) s += __shfl_xor_sync(0xffffffffu, s, o);
            if (l == 0) q[w][qq] = cosf(s + bbv[qq] + th[qq]);
        }
    }
    __syncthreads();

    if (tid < NQ) {
        float f = 1.0f / (1.0f + expf(-q[0][tid]));
        float g = tanhf(q[1][tid]);
        float o = 1.0f / (1.0f + expf(-q[2][tid]));
        hout[tid] = o * tanhf(f * g);
    }
    __syncthreads();

    if (tid < TTAG) {
        float s = bt[tid];
#pragma unroll
        for (int qq = 0; qq < NQ; qq++) s += hout[qq] * Wt[tid * NQ + qq];
        lg[tid] = s;
    }
    __syncthreads();

    if (tid == 0) {
        float m = lg[0];
        for (int i = 1; i < TTAG; i++) m = fmaxf(m, lg[i]);
        float sum = 0.0f;
        for (int i = 0; i < TTAG; i++) sum += expf(lg[i] - m);
        lse = m + logf(sum);
    }
    __syncthreads();

    if (tid < TTAG) out[(size_t)b * TTAG + tid] = lg[tid] - lse;
}

// ---------------------------------------------------------------------------
extern "C" void kernel_launch(void* const* d_in, const int* in_sizes, int n_in,
                              void* d_out, int out_size)
{
    const float* x   = (const float*)d_in[0];
    const float* Wih = (const float*)d_in[1];
    const float* Whh = (const float*)d_in[2];
    const float* bih = (const float*)d_in[3];
    const float* bhh = (const float*)d_in[4];
    const float* Wf  = (const float*)d_in[5];
    const float* bf  = (const float*)d_in[6];
    const float* Wu  = (const float*)d_in[9];
    const float* bu  = (const float*)d_in[10];
    const float* Wo  = (const float*)d_in[11];
    const float* bo  = (const float*)d_in[12];
    const float* thf = (const float*)d_in[13];
    const float* thu = (const float*)d_in[15];
    const float* tho = (const float*)d_in[16];
    const float* Wt  = (const float*)d_in[17];
    const float* bt  = (const float*)d_in[18];
    float* out = (float*)d_out;

    cudaFuncSetAttribute(lstm_persistent,
                         cudaFuncAttributeMaxDynamicSharedMemorySize, RT_TOT * 4);

    dim3 pg(16, SS);   // 16 n-blocks x 512 timesteps
    precompute_mma<<<pg, 256>>>(x, Wih, bih, bhh);
    lstm_persistent<<<128, 256, RT_TOT * 4>>>(Whh);
    final_kernel<<<BB, 128>>>(Wf, bf, Wu, bu, Wo, bo, thf, thu, tho, Wt, bt, out);
}

// round 8
// speedup vs baseline: 2.3233x; 1.0980x over previous
#include <cuda_runtime.h>
#include <math.h>
#include <stdint.h>

#define BB 128
#define SS 512
#define HH 512
#define NQ 8
#define TTAG 50

// ---------------------------------------------------------------------------
// Scratch
// ---------------------------------------------------------------------------
__device__ float g_Xz[(size_t)SS * 4 * BB * HH];   // [t][gate][b][j]
__device__ float g_h2[2][BB * HH];                 // [buf][b][j]
__device__ int            g_cnt[4];
__device__ volatile int   g_gen[4];

extern __shared__ float smemf[];

__device__ __forceinline__ float sigf(float x) { return 1.0f / (1.0f + __expf(-x)); }
__device__ __forceinline__ float tanhf_fast(float x) {
    return 1.0f - 2.0f / (__expf(2.0f * x) + 1.0f);
}
__device__ __forceinline__ uint32_t smem_u32(const void* p) {
    uint32_t a;
    asm("{ .reg .u64 t; cvta.to.shared.u64 t, %1; cvt.u32.u64 %0, t; }" : "=r"(a) : "l"(p));
    return a;
}
__device__ __forceinline__ void cp16(uint32_t dst, const void* src) {
    asm volatile("cp.async.cg.shared.global [%0], [%1], 16;" :: "r"(dst), "l"(src) : "memory");
}
__device__ __forceinline__ void cp_commit() {
    asm volatile("cp.async.commit_group;" ::: "memory");
}
__device__ __forceinline__ void cp_wait0() {
    asm volatile("cp.async.wait_group 0;" ::: "memory");
}
__device__ __forceinline__ void cp_wait1() {
    asm volatile("cp.async.wait_group 1;" ::: "memory");
}

#define MMA_TF32(acc, a, b0v, b1v) \
    asm volatile( \
        "mma.sync.aligned.m16n8k8.row.col.f32.tf32.tf32.f32 " \
        "{%0,%1,%2,%3}, {%4,%5,%6,%7}, {%8,%9}, {%0,%1,%2,%3};" \
        : "+f"((acc)[0]), "+f"((acc)[1]), "+f"((acc)[2]), "+f"((acc)[3]) \
        : "r"((a)[0]), "r"((a)[1]), "r"((a)[2]), "r"((a)[3]), \
          "r"(b0v), "r"(b1v))

// ---------------------------------------------------------------------------
// Precompute: g_Xz[t][gate][b][j] = x@Wih^T + bih + bhh, tf32 mma.sync,
// 2-stage cp.async double buffer. Per CTA: M=128 (batch), N=128 cols, K=512.
// Natural [row][k] smem layout, row stride 20 floats (conflict-free frags).
// ---------------------------------------------------------------------------
__global__ __launch_bounds__(256) void precompute_mma(
    const float* __restrict__ x, const float* __restrict__ Wih,
    const float* __restrict__ bih, const float* __restrict__ bhh)
{
    __shared__ float As[2][128 * 20];
    __shared__ float Bs[2][128 * 20];
    __shared__ float sbias[128];

    const int t   = blockIdx.y;
    const int n0  = blockIdx.x * 128;
    const int tid = threadIdx.x;
    const int wid = tid >> 5, lane = tid & 31;
    const int wm = wid & 3, wn = wid >> 2;
    const int mb = wm * 32, nb = wn * 64;
    const int g  = lane >> 2, tg = lane & 3;

    if (tid < 128) sbias[tid] = bih[n0 + tid] + bhh[n0 + tid];

    float acc[2][8][4];
#pragma unroll
    for (int mf = 0; mf < 2; mf++)
#pragma unroll
        for (int nf = 0; nf < 8; nf++)
#pragma unroll
            for (int r = 0; r < 4; r++) acc[mf][nf][r] = 0.0f;

    const int la_b = tid >> 1, la_k = (tid & 1) * 8;
    const float* xrow = x + ((size_t)la_b * SS + t) * HH + la_k;
    const float* wrow = Wih + (size_t)(n0 + la_b) * HH + la_k;
    const uint32_t a_dst0 = smem_u32(&As[0][la_b * 20 + la_k]);
    const uint32_t a_dst1 = smem_u32(&As[1][la_b * 20 + la_k]);
    const uint32_t b_dst0 = smem_u32(&Bs[0][la_b * 20 + la_k]);
    const uint32_t b_dst1 = smem_u32(&Bs[1][la_b * 20 + la_k]);

    // issue chunk 0
    cp16(a_dst0, xrow);       cp16(a_dst0 + 16, xrow + 4);
    cp16(b_dst0, wrow);       cp16(b_dst0 + 16, wrow + 4);
    cp_commit();

    for (int kc = 0; kc < 32; kc++) {
        const int buf = kc & 1;
        if (kc < 31) {
            const int ko = (kc + 1) * 16;
            uint32_t ad = buf ? a_dst0 : a_dst1;
            uint32_t bd = buf ? b_dst0 : b_dst1;
            cp16(ad, xrow + ko);       cp16(ad + 16, xrow + ko + 4);
            cp16(bd, wrow + ko);       cp16(bd + 16, wrow + ko + 4);
            cp_commit();
            cp_wait1();
        } else {
            cp_wait0();
        }
        __syncthreads();

        const float* Ab = As[buf];
        const float* Bb = Bs[buf];
#pragma unroll
        for (int ks = 0; ks < 16; ks += 8) {
            uint32_t afr[2][4];
#pragma unroll
            for (int mf = 0; mf < 2; mf++) {
                int r0 = (mb + mf * 16 + g) * 20, r1 = r0 + 8 * 20;
                afr[mf][0] = __float_as_uint(Ab[r0 + ks + tg]);
                afr[mf][1] = __float_as_uint(Ab[r1 + ks + tg]);
                afr[mf][2] = __float_as_uint(Ab[r0 + ks + tg + 4]);
                afr[mf][3] = __float_as_uint(Ab[r1 + ks + tg + 4]);
            }
#pragma unroll
            for (int nf = 0; nf < 8; nf++) {
                int cn = (nb + nf * 8 + g) * 20;
                uint32_t bf0 = __float_as_uint(Bb[cn + ks + tg]);
                uint32_t bf1 = __float_as_uint(Bb[cn + ks + tg + 4]);
#pragma unroll
                for (int mf = 0; mf < 2; mf++) MMA_TF32(acc[mf][nf], afr[mf], bf0, bf1);
            }
        }
        __syncthreads();
    }

    // epilogue -> g_Xz[t][gate][b][j]
#pragma unroll
    for (int mf = 0; mf < 2; mf++) {
#pragma unroll
        for (int nf = 0; nf < 8; nf++) {
            int lcol = nb + nf * 8 + 2 * tg;
            int row0 = mb + mf * 16 + g;
            int row1 = row0 + 8;
#pragma unroll
            for (int cc = 0; cc < 2; cc++) {
                int gcol = n0 + lcol + cc;
                int gate = gcol >> 9, j = gcol & 511;
                float bias = sbias[lcol + cc];
                float* base = g_Xz + ((size_t)t * 4 + gate) * BB * HH + j;
                base[(size_t)row0 * HH] = acc[mf][nf][cc]     + bias;
                base[(size_t)row1 * HH] = acc[mf][nf][2 + cc] + bias;
            }
        }
    }
}

// ---------------------------------------------------------------------------
// Persistent LSTM recurrence — tensor-core per-step GEMM, fused reduction.
// 128 CTAs = 32 col-groups (64 cols) x 4 batch-groups (32 b).
// 8 warps = 2 n-halves x 4 k-slices; partials in smem; fusion reads partials
// directly (no zb stage). cp.async.cg h staging. j-fast fusion lanes ->
// 64B-coalesced Xz reads and h writes.
// ---------------------------------------------------------------------------
#define RT_WS   0                        // Ws[c][k] stride 516: 64*516
#define RT_HS   (64 * 516)               // hs[b][k] stride 516: 32*516 (partials reuse)
#define RT_CS   (RT_HS + 32 * 516)       // cs[bb][j]: 32*16
#define RT_TOT  (RT_CS + 32 * 16)        // 50048 floats = 200192 B

__device__ __forceinline__ void group_bar(int bg) {
    __threadfence();
    __syncthreads();
    if (threadIdx.x == 0) {
        int g = g_gen[bg];
        if (atomicAdd(&g_cnt[bg], 1) == 31) {
            g_cnt[bg] = 0;
            __threadfence();
            g_gen[bg] = g + 1;
        } else {
            while (g_gen[bg] == g) { __nanosleep(64); }
        }
        __threadfence();
    }
    __syncthreads();
}

__global__ void __launch_bounds__(256, 1) lstm_persistent(const float* __restrict__ Whh)
{
    float* Ws = smemf + RT_WS;
    float* hs = smemf + RT_HS;     // partial buffer after MMA
    float* cs = smemf + RT_CS;

    const int tid = threadIdx.x;
    const int cg = blockIdx.x & 31, bg = blockIdx.x >> 5;
    const int j0 = cg * 16, b0 = bg * 32;
    const int w = tid >> 5, lane = tid & 31;
    const int g = lane >> 2, tg = lane & 3;
    const uint32_t hs_u32 = smem_u32(hs);

    // Load Whh slice: Ws[c][k], c = gate*16 + jj
    for (int i = tid; i < 64 * 128; i += 256) {
        int c = i >> 7, k4 = (i & 127) * 4;
        int gate = c >> 4, jj = c & 15;
        float4 v = *(const float4*)(Whh + (size_t)(gate * HH + j0 + jj) * HH + k4);
        *(float4*)&Ws[c * 516 + k4] = v;
    }
    for (int i = tid; i < 512; i += 256) cs[i] = 0.0f;
    for (int i = tid; i < 32 * HH; i += 256) {
        int bb = i >> 9, j = i & 511;
        g_h2[0][(size_t)(b0 + bb) * HH + j] = 0.0f;
    }
    group_bar(bg);

    const int ng  = w & 1;          // n-half: cols [32ng, 32ng+32)
    const int ksl = w >> 1;         // k-slice: [128ksl, 128ksl+128)
    const int nb  = ng * 32;
    const int kb  = ksl * 128;

    for (int t = 0; t < SS; t++) {
        const float* __restrict__ hcur = g_h2[t & 1];
        float* __restrict__ hnxt = g_h2[(t + 1) & 1];

        // prefetch Xz (j-fast lanes -> 64B coalesced)
        float xzv[2][4];
#pragma unroll
        for (int it = 0; it < 2; it++) {
            int idx = tid + it * 256;
            int j = idx & 15, bb = idx >> 4;
#pragma unroll
            for (int gt = 0; gt < 4; gt++)
                xzv[it][gt] = __ldg(g_Xz + ((size_t)t * 4 + gt) * BB * HH
                                    + (size_t)(b0 + bb) * HH + j0 + j);
        }

        // stage h -> hs[b][k] via cp.async.cg (L2-direct)
        for (int i = tid; i < 32 * 128; i += 256) {
            int bb = i >> 7, k4 = (i & 127) * 4;
            cp16(hs_u32 + (bb * 516 + k4) * 4, hcur + (size_t)(b0 + bb) * HH + k4);
        }
        cp_commit();
        cp_wait0();
        __syncthreads();

        // MMA: warp tile [32b x 32c] over its 128-k slice
        float acc[2][4][4];
#pragma unroll
        for (int mf = 0; mf < 2; mf++)
#pragma unroll
            for (int nf = 0; nf < 4; nf++)
#pragma unroll
                for (int r = 0; r < 4; r++) acc[mf][nf][r] = 0.0f;

#pragma unroll 4
        for (int kf = 0; kf < 16; kf++) {
            const int k = kb + kf * 8;
            uint32_t afr[2][4];
#pragma unroll
            for (int mf = 0; mf < 2; mf++) {
                int r0 = mf * 16 + g, r1 = r0 + 8;
                afr[mf][0] = __float_as_uint(hs[r0 * 516 + k + tg]);
                afr[mf][1] = __float_as_uint(hs[r1 * 516 + k + tg]);
                afr[mf][2] = __float_as_uint(hs[r0 * 516 + k + tg + 4]);
                afr[mf][3] = __float_as_uint(hs[r1 * 516 + k + tg + 4]);
            }
#pragma unroll
            for (int nf = 0; nf < 4; nf++) {
                int c = nb + nf * 8 + g;
                uint32_t bf0 = __float_as_uint(Ws[c * 516 + k + tg]);
                uint32_t bf1 = __float_as_uint(Ws[c * 516 + k + tg + 4]);
#pragma unroll
                for (int mf = 0; mf < 2; mf++) MMA_TF32(acc[mf][nf], afr[mf], bf0, bf1);
            }
        }
        __syncthreads();   // hs reads done; reuse as partial buffer

        // partials: part[(ksl*64 + c)*33 + brow]
#pragma unroll
        for (int mf = 0; mf < 2; mf++)
#pragma unroll
            for (int nf = 0; nf < 4; nf++) {
                int cb = nb + nf * 8 + 2 * tg;
                int r0 = mf * 16 + g, r1 = r0 + 8;
                hs[(ksl * 64 + cb)     * 33 + r0] = acc[mf][nf][0];
                hs[(ksl * 64 + cb + 1) * 33 + r0] = acc[mf][nf][1];
                hs[(ksl * 64 + cb)     * 33 + r1] = acc[mf][nf][2];
                hs[(ksl * 64 + cb + 1) * 33 + r1] = acc[mf][nf][3];
            }
        __syncthreads();

        // fused reduce + gate + h/c update (j-fast lanes)
#pragma unroll
        for (int it = 0; it < 2; it++) {
            int idx = tid + it * 256;
            int j = idx & 15, bb = idx >> 4;
            float z[4];
#pragma unroll
            for (int gt = 0; gt < 4; gt++) {
                int c = gt * 16 + j;
                z[gt] = hs[(c)       * 33 + bb] + hs[(64 + c)  * 33 + bb]
                      + hs[(128 + c) * 33 + bb] + hs[(192 + c) * 33 + bb]
                      + xzv[it][gt];
            }
            float cold = cs[bb * 16 + j];
            float cn = sigf(z[1]) * cold + sigf(z[0]) * tanhf_fast(z[2]);
            cs[bb * 16 + j] = cn;
            hnxt[(size_t)(b0 + bb) * HH + j0 + j] = sigf(z[3]) * tanhf_fast(cn);
        }
        group_bar(bg);
    }
}

// ---------------------------------------------------------------------------
// Quantum head + log_softmax (final h in g_h2[0], layout [b][j])
// ---------------------------------------------------------------------------
__global__ __launch_bounds__(128) void final_kernel(
    const float* __restrict__ Wf, const float* __restrict__ bf,
    const float* __restrict__ Wu, const float* __restrict__ bu,
    const float* __restrict__ Wo, const float* __restrict__ bo,
    const float* __restrict__ thf, const float* __restrict__ thu,
    const float* __restrict__ tho,
    const float* __restrict__ Wt, const float* __restrict__ bt,
    float* __restrict__ out)
{
    __shared__ float sx[HH];
    __shared__ float q[3][NQ];
    __shared__ float hout[NQ];
    __shared__ float lg[TTAG];
    __shared__ float lse;

    const int b = blockIdx.x;
    const int tid = threadIdx.x;

    for (int k = tid; k < HH; k += 128) sx[k] = g_h2[0][(size_t)b * HH + k];
    __syncthreads();

    const int w = tid >> 5, l = tid & 31;
    if (w < 3) {
        const float* W   = (w == 0) ? Wf : (w == 1) ? Wu : Wo;
        const float* bbv = (w == 0) ? bf : (w == 1) ? bu : bo;
        const float* th  = (w == 0) ? thf : (w == 1) ? thu : tho;
        for (int qq = 0; qq < NQ; qq++) {
            float s = 0.0f;
            for (int k = l; k < HH; k += 32) s += sx[k] * W[qq * HH + k];
#pragma unroll
            for (int o = 16; o > 0; o >>= 1) s += __shfl_xor_sync(0xffffffffu, s, o);
            if (l == 0) q[w][qq] = cosf(s + bbv[qq] + th[qq]);
        }
    }
    __syncthreads();

    if (tid < NQ) {
        float f = 1.0f / (1.0f + expf(-q[0][tid]));
        float g = tanhf(q[1][tid]);
        float o = 1.0f / (1.0f + expf(-q[2][tid]));
        hout[tid] = o * tanhf(f * g);
    }
    __syncthreads();

    if (tid < TTAG) {
        float s = bt[tid];
#pragma unroll
        for (int qq = 0; qq < NQ; qq++) s += hout[qq] * Wt[tid * NQ + qq];
        lg[tid] = s;
    }
    __syncthreads();

    if (tid == 0) {
        float m = lg[0];
        for (int i = 1; i < TTAG; i++) m = fmaxf(m, lg[i]);
        float sum = 0.0f;
        for (int i = 0; i < TTAG; i++) sum += expf(lg[i] - m);
        lse = m + logf(sum);
    }
    __syncthreads();

    if (tid < TTAG) out[(size_t)b * TTAG + tid] = lg[tid] - lse;
}

// ---------------------------------------------------------------------------
extern "C" void kernel_launch(void* const* d_in, const int* in_sizes, int n_in,
                              void* d_out, int out_size)
{
    const float* x   = (const float*)d_in[0];
    const float* Wih = (const float*)d_in[1];
    const float* Whh = (const float*)d_in[2];
    const float* bih = (const float*)d_in[3];
    const float* bhh = (const float*)d_in[4];
    const float* Wf  = (const float*)d_in[5];
    const float* bf  = (const float*)d_in[6];
    const float* Wu  = (const float*)d_in[9];
    const float* bu  = (const float*)d_in[10];
    const float* Wo  = (const float*)d_in[11];
    const float* bo  = (const float*)d_in[12];
    const float* thf = (const float*)d_in[13];
    const float* thu = (const float*)d_in[15];
    const float* tho = (const float*)d_in[16];
    const float* Wt  = (const float*)d_in[17];
    const float* bt  = (const float*)d_in[18];
    float* out = (float*)d_out;

    cudaFuncSetAttribute(lstm_persistent,
                         cudaFuncAttributeMaxDynamicSharedMemorySize, RT_TOT * 4);

    dim3 pg(16, SS);   // 16 n-blocks x 512 timesteps
    precompute_mma<<<pg, 256>>>(x, Wih, bih, bhh);
    lstm_persistent<<<128, 256, RT_TOT * 4>>>(Whh);
    final_kernel<<<BB, 128>>>(Wf, bf, Wu, bu, Wo, bo, thf, thu, tho, Wt, bt, out);
}